// round 1
// baseline (speedup 1.0000x reference)
#include <cuda_runtime.h>

// CrossCompress: B=16384 rows, D=128.
// item_out  = v*(e.w_vv) + e*(v.w_ev) + bias_v
// entity_out= v*(e.w_ve) + e*(v.w_ee) + bias_e
// One warp per row. Lane l owns elements [4l, 4l+4) as a float4.
// 4 dot products reduced simultaneously via 5 butterfly shuffles.

#define B_ROWS 16384
#define D_DIM  128

__global__ __launch_bounds__(256)
void crosscompress_kernel(const float4* __restrict__ v_in,
                          const float4* __restrict__ e_in,
                          const float4* __restrict__ w_vv,
                          const float4* __restrict__ w_ve,
                          const float4* __restrict__ w_ev,
                          const float4* __restrict__ w_ee,
                          const float4* __restrict__ bias_v,
                          const float4* __restrict__ bias_e,
                          float4* __restrict__ out_item,
                          float4* __restrict__ out_ent)
{
    const int gtid = blockIdx.x * blockDim.x + threadIdx.x;
    const int row  = gtid >> 5;           // warp id == row
    const int lane = gtid & 31;
    if (row >= B_ROWS) return;

    const int idx = row * 32 + lane;      // float4 index into [B, D] tensor

    // Row data (coalesced 128B per warp per tensor)
    const float4 v4 = v_in[idx];
    const float4 e4 = e_in[idx];

    // Weights: 512B each, L1-resident after first warp on each SM
    const float4 wvv = __ldg(&w_vv[lane]);
    const float4 wve = __ldg(&w_ve[lane]);
    const float4 wev = __ldg(&w_ev[lane]);
    const float4 wee = __ldg(&w_ee[lane]);

    // Per-lane partial dots
    float d_vv = e4.x * wvv.x + e4.y * wvv.y + e4.z * wvv.z + e4.w * wvv.w; // e . w_vv
    float d_ev = v4.x * wev.x + v4.y * wev.y + v4.z * wev.z + v4.w * wev.w; // v . w_ev
    float d_ve = e4.x * wve.x + e4.y * wve.y + e4.z * wve.z + e4.w * wve.w; // e . w_ve
    float d_ee = v4.x * wee.x + v4.y * wee.y + v4.z * wee.z + v4.w * wee.w; // v . w_ee

    // Butterfly reduce all 4 dots across the warp
    #pragma unroll
    for (int off = 16; off > 0; off >>= 1) {
        d_vv += __shfl_xor_sync(0xFFFFFFFFu, d_vv, off);
        d_ev += __shfl_xor_sync(0xFFFFFFFFu, d_ev, off);
        d_ve += __shfl_xor_sync(0xFFFFFFFFu, d_ve, off);
        d_ee += __shfl_xor_sync(0xFFFFFFFFu, d_ee, off);
    }

    const float4 bv = __ldg(&bias_v[lane]);
    const float4 be = __ldg(&bias_e[lane]);

    float4 oi, oe;
    oi.x = v4.x * d_vv + e4.x * d_ev + bv.x;
    oi.y = v4.y * d_vv + e4.y * d_ev + bv.y;
    oi.z = v4.z * d_vv + e4.z * d_ev + bv.z;
    oi.w = v4.w * d_vv + e4.w * d_ev + bv.w;

    oe.x = v4.x * d_ve + e4.x * d_ee + be.x;
    oe.y = v4.y * d_ve + e4.y * d_ee + be.y;
    oe.z = v4.z * d_ve + e4.z * d_ee + be.z;
    oe.w = v4.w * d_ve + e4.w * d_ee + be.w;

    out_item[idx] = oi;
    out_ent[idx]  = oe;
}

extern "C" void kernel_launch(void* const* d_in, const int* in_sizes, int n_in,
                              void* d_out, int out_size)
{
    const float4* v_in   = (const float4*)d_in[0]; // item_embedding [B,D,1]
    const float4* e_in   = (const float4*)d_in[1]; // entity_embedding [B,D,1]
    const float4* w_vv   = (const float4*)d_in[2];
    const float4* w_ve   = (const float4*)d_in[3];
    const float4* w_ev   = (const float4*)d_in[4];
    const float4* w_ee   = (const float4*)d_in[5];
    const float4* bias_v = (const float4*)d_in[6];
    const float4* bias_e = (const float4*)d_in[7];

    float* out = (float*)d_out;
    float4* out_item = (float4*)out;                       // first B*D floats
    float4* out_ent  = (float4*)(out + B_ROWS * D_DIM);    // second B*D floats

    // one warp per row, 8 warps per block
    const int threads = 256;
    const int total_threads = B_ROWS * 32;
    const int blocks = (total_threads + threads - 1) / threads; // 2048

    crosscompress_kernel<<<blocks, threads>>>(v_in, e_in, w_vv, w_ve, w_ev, w_ee,
                                              bias_v, bias_e, out_item, out_ent);
}

// round 2
// speedup vs baseline: 1.0623x; 1.0623x over previous
#include <cuda_runtime.h>

// CrossCompress: B=16384 rows, D=128.
// item_out   = v*(e.w_vv) + e*(v.w_ev) + bias_v
// entity_out = v*(e.w_ve) + e*(v.w_ee) + bias_e
//
// R2 design: one warp processes 4 consecutive rows. Lane l owns float4 l of
// each row. 8 batched LDG.128s (MLP=8), 16 parallel butterfly-reduction
// chains, then fused combine + 8 stores. Weights/biases are L1-resident.

#define B_ROWS 16384
#define D_DIM  128
#define ROWS_PER_WARP 4

__global__ __launch_bounds__(256)
void crosscompress_kernel(const float4* __restrict__ v_in,
                          const float4* __restrict__ e_in,
                          const float4* __restrict__ w_vv,
                          const float4* __restrict__ w_ve,
                          const float4* __restrict__ w_ev,
                          const float4* __restrict__ w_ee,
                          const float4* __restrict__ bias_v,
                          const float4* __restrict__ bias_e,
                          float4* __restrict__ out_item,
                          float4* __restrict__ out_ent)
{
    const int gtid   = blockIdx.x * blockDim.x + threadIdx.x;
    const int warp   = gtid >> 5;
    const int lane   = gtid & 31;
    const int row0   = warp * ROWS_PER_WARP;   // grid sized exactly, no tail

    // Batch all data loads first: 8 independent LDG.128 (MLP=8)
    float4 v4[ROWS_PER_WARP], e4[ROWS_PER_WARP];
    #pragma unroll
    for (int r = 0; r < ROWS_PER_WARP; r++) {
        const int idx = (row0 + r) * 32 + lane;
        v4[r] = v_in[idx];
        e4[r] = e_in[idx];
    }

    // Weights: 512B each, L1-resident after first touch per SM
    const float4 wvv = __ldg(&w_vv[lane]);
    const float4 wev = __ldg(&w_ev[lane]);
    const float4 wve = __ldg(&w_ve[lane]);
    const float4 wee = __ldg(&w_ee[lane]);

    // Per-lane partial dots: 16 independent accumulators
    float d_vv[ROWS_PER_WARP], d_ev[ROWS_PER_WARP];
    float d_ve[ROWS_PER_WARP], d_ee[ROWS_PER_WARP];
    #pragma unroll
    for (int r = 0; r < ROWS_PER_WARP; r++) {
        d_vv[r] = e4[r].x * wvv.x + e4[r].y * wvv.y + e4[r].z * wvv.z + e4[r].w * wvv.w;
        d_ev[r] = v4[r].x * wev.x + v4[r].y * wev.y + v4[r].z * wev.z + v4[r].w * wev.w;
        d_ve[r] = e4[r].x * wve.x + e4[r].y * wve.y + e4[r].z * wve.z + e4[r].w * wve.w;
        d_ee[r] = v4[r].x * wee.x + v4[r].y * wee.y + v4[r].z * wee.z + v4[r].w * wee.w;
    }

    // Butterfly-reduce all 16 values; 16 parallel chains hide SHFL latency
    #pragma unroll
    for (int off = 16; off > 0; off >>= 1) {
        #pragma unroll
        for (int r = 0; r < ROWS_PER_WARP; r++) {
            d_vv[r] += __shfl_xor_sync(0xFFFFFFFFu, d_vv[r], off);
            d_ev[r] += __shfl_xor_sync(0xFFFFFFFFu, d_ev[r], off);
            d_ve[r] += __shfl_xor_sync(0xFFFFFFFFu, d_ve[r], off);
            d_ee[r] += __shfl_xor_sync(0xFFFFFFFFu, d_ee[r], off);
        }
    }

    const float4 bv = __ldg(&bias_v[lane]);
    const float4 be = __ldg(&bias_e[lane]);

    #pragma unroll
    for (int r = 0; r < ROWS_PER_WARP; r++) {
        const int idx = (row0 + r) * 32 + lane;
        float4 oi, oe;
        oi.x = v4[r].x * d_vv[r] + e4[r].x * d_ev[r] + bv.x;
        oi.y = v4[r].y * d_vv[r] + e4[r].y * d_ev[r] + bv.y;
        oi.z = v4[r].z * d_vv[r] + e4[r].z * d_ev[r] + bv.z;
        oi.w = v4[r].w * d_vv[r] + e4[r].w * d_ev[r] + bv.w;

        oe.x = v4[r].x * d_ve[r] + e4[r].x * d_ee[r] + be.x;
        oe.y = v4[r].y * d_ve[r] + e4[r].y * d_ee[r] + be.y;
        oe.z = v4[r].z * d_ve[r] + e4[r].z * d_ee[r] + be.z;
        oe.w = v4[r].w * d_ve[r] + e4[r].w * d_ee[r] + be.w;

        out_item[idx] = oi;
        out_ent[idx]  = oe;
    }
}

extern "C" void kernel_launch(void* const* d_in, const int* in_sizes, int n_in,
                              void* d_out, int out_size)
{
    const float4* v_in   = (const float4*)d_in[0];
    const float4* e_in   = (const float4*)d_in[1];
    const float4* w_vv   = (const float4*)d_in[2];
    const float4* w_ve   = (const float4*)d_in[3];
    const float4* w_ev   = (const float4*)d_in[4];
    const float4* w_ee   = (const float4*)d_in[5];
    const float4* bias_v = (const float4*)d_in[6];
    const float4* bias_e = (const float4*)d_in[7];

    float* out = (float*)d_out;
    float4* out_item = (float4*)out;
    float4* out_ent  = (float4*)(out + B_ROWS * D_DIM);

    // 8 warps/block, 4 rows/warp -> 32 rows/block -> 512 blocks exactly
    const int threads = 256;
    const int blocks  = B_ROWS / (8 * ROWS_PER_WARP);   // 512

    crosscompress_kernel<<<blocks, threads>>>(v_in, e_in, w_vv, w_ve, w_ev, w_ee,
                                              bias_v, bias_e, out_item, out_ent);
}

// round 3
// speedup vs baseline: 1.2583x; 1.1845x over previous
#include <cuda_runtime.h>

// CrossCompress: B=16384 rows, D=128.
// item_out   = v*(e.w_vv) + e*(v.w_ev) + bias_v
// entity_out = v*(e.w_ve) + e*(v.w_ee) + bias_e
//
// R3: 4 rows/warp (MLP=8 batched LDG.128) + 128-thread blocks so 8 blocks/SM
// fit at 64 regs -> 32 resident warps/SM (~50% occ) with a grid of 1024.

#define B_ROWS 16384
#define D_DIM  128
#define ROWS_PER_WARP 4

__global__ __launch_bounds__(128, 8)
void crosscompress_kernel(const float4* __restrict__ v_in,
                          const float4* __restrict__ e_in,
                          const float4* __restrict__ w_vv,
                          const float4* __restrict__ w_ve,
                          const float4* __restrict__ w_ev,
                          const float4* __restrict__ w_ee,
                          const float4* __restrict__ bias_v,
                          const float4* __restrict__ bias_e,
                          float4* __restrict__ out_item,
                          float4* __restrict__ out_ent)
{
    const int gtid = blockIdx.x * blockDim.x + threadIdx.x;
    const int warp = gtid >> 5;
    const int lane = gtid & 31;
    const int row0 = warp * ROWS_PER_WARP;     // grid sized exactly

    // Batch all row loads: 8 independent LDG.128 (MLP=8)
    float4 v4[ROWS_PER_WARP], e4[ROWS_PER_WARP];
    #pragma unroll
    for (int r = 0; r < ROWS_PER_WARP; r++) {
        const int idx = (row0 + r) * 32 + lane;
        v4[r] = v_in[idx];
        e4[r] = e_in[idx];
    }

    // Weights: 512B each, L1-resident after first touch per SM
    const float4 wvv = __ldg(&w_vv[lane]);
    const float4 wev = __ldg(&w_ev[lane]);
    const float4 wve = __ldg(&w_ve[lane]);
    const float4 wee = __ldg(&w_ee[lane]);

    // 16 independent per-lane partial dots
    float d_vv[ROWS_PER_WARP], d_ev[ROWS_PER_WARP];
    float d_ve[ROWS_PER_WARP], d_ee[ROWS_PER_WARP];
    #pragma unroll
    for (int r = 0; r < ROWS_PER_WARP; r++) {
        d_vv[r] = e4[r].x * wvv.x + e4[r].y * wvv.y + e4[r].z * wvv.z + e4[r].w * wvv.w;
        d_ev[r] = v4[r].x * wev.x + v4[r].y * wev.y + v4[r].z * wev.z + v4[r].w * wev.w;
        d_ve[r] = e4[r].x * wve.x + e4[r].y * wve.y + e4[r].z * wve.z + e4[r].w * wve.w;
        d_ee[r] = v4[r].x * wee.x + v4[r].y * wee.y + v4[r].z * wee.z + v4[r].w * wee.w;
    }

    // Butterfly-reduce all 16 values; 16 parallel chains hide SHFL latency
    #pragma unroll
    for (int off = 16; off > 0; off >>= 1) {
        #pragma unroll
        for (int r = 0; r < ROWS_PER_WARP; r++) {
            d_vv[r] += __shfl_xor_sync(0xFFFFFFFFu, d_vv[r], off);
            d_ev[r] += __shfl_xor_sync(0xFFFFFFFFu, d_ev[r], off);
            d_ve[r] += __shfl_xor_sync(0xFFFFFFFFu, d_ve[r], off);
            d_ee[r] += __shfl_xor_sync(0xFFFFFFFFu, d_ee[r], off);
        }
    }

    const float4 bv = __ldg(&bias_v[lane]);
    const float4 be = __ldg(&bias_e[lane]);

    #pragma unroll
    for (int r = 0; r < ROWS_PER_WARP; r++) {
        const int idx = (row0 + r) * 32 + lane;
        float4 oi, oe;
        oi.x = v4[r].x * d_vv[r] + e4[r].x * d_ev[r] + bv.x;
        oi.y = v4[r].y * d_vv[r] + e4[r].y * d_ev[r] + bv.y;
        oi.z = v4[r].z * d_vv[r] + e4[r].z * d_ev[r] + bv.z;
        oi.w = v4[r].w * d_vv[r] + e4[r].w * d_ev[r] + bv.w;

        oe.x = v4[r].x * d_ve[r] + e4[r].x * d_ee[r] + be.x;
        oe.y = v4[r].y * d_ve[r] + e4[r].y * d_ee[r] + be.y;
        oe.z = v4[r].z * d_ve[r] + e4[r].z * d_ee[r] + be.z;
        oe.w = v4[r].w * d_ve[r] + e4[r].w * d_ee[r] + be.w;

        out_item[idx] = oi;
        out_ent[idx]  = oe;
    }
}

extern "C" void kernel_launch(void* const* d_in, const int* in_sizes, int n_in,
                              void* d_out, int out_size)
{
    const float4* v_in   = (const float4*)d_in[0];
    const float4* e_in   = (const float4*)d_in[1];
    const float4* w_vv   = (const float4*)d_in[2];
    const float4* w_ve   = (const float4*)d_in[3];
    const float4* w_ev   = (const float4*)d_in[4];
    const float4* w_ee   = (const float4*)d_in[5];
    const float4* bias_v = (const float4*)d_in[6];
    const float4* bias_e = (const float4*)d_in[7];

    float* out = (float*)d_out;
    float4* out_item = (float4*)out;
    float4* out_ent  = (float4*)(out + B_ROWS * D_DIM);

    // 4 warps/block, 4 rows/warp -> 16 rows/block -> 1024 blocks
    const int threads = 128;
    const int blocks  = B_ROWS / (4 * ROWS_PER_WARP);   // 1024

    crosscompress_kernel<<<blocks, threads>>>(v_in, e_in, w_vv, w_ve, w_ev, w_ee,
                                              bias_v, bias_e, out_item, out_ent);
}